// round 5
// baseline (speedup 1.0000x reference)
#include <cuda_runtime.h>
#include <cstdint>

// ---------------- problem constants ----------------
#define NEXP   8
#define DDIM   1024
#define HDIM   2048
#define TMAX   8192
#define BM     128
#define BN     128
#define BK     32
#define SLOT_MAX (2*TMAX + NEXP*BM)   // 17408

#define APITCH 36       // As row pitch (u32): 36*4=144B, 16B aligned, frag lanes 4g+q conflict-free
#define BPITCH 136      // Bs row pitch (u32): 136 mod 32 = 8 -> frag lanes 8q+g conflict-free
#define NSTAGE 3
#define SMEM_GEMM (NSTAGE * (BM*APITCH + BK*BPITCH) * 4)   // 107520 B

// ---------------- device scratch ----------------
__device__ int   g_counts[NEXP];
__device__ int   g_fill[NEXP];
__device__ int   g_off[NEXP + 1];
__device__ int   g_tok[SLOT_MAX];
__device__ int   g_slot[2 * TMAX];
__device__ int   g_e[2 * TMAX];
__device__ float g_wt[2 * TMAX];
__device__ float g_h[(size_t)SLOT_MAX * HDIM];   // tf32-rounded hidden acts
__device__ float g_y[(size_t)SLOT_MAX * DDIM];   // fp32 expert outputs
__device__ float g_xt[(size_t)TMAX * DDIM];      // tf32-rounded x
__device__ float g_w1t[(size_t)NEXP * DDIM * HDIM];  // tf32-rounded W1
__device__ float g_w2t[(size_t)NEXP * HDIM * DDIM];  // tf32-rounded W2

// ---------------- helpers ----------------
__device__ __forceinline__ uint32_t f2tf32(float f) {
    uint32_t r;
    asm("cvt.rna.tf32.f32 %0, %1;" : "=r"(r) : "f"(f));
    return r;
}
__device__ __forceinline__ float f2tf32f(float f) {
    return __uint_as_float(f2tf32(f));
}
__device__ __forceinline__ void cp16(uint32_t dst, const void* src, bool valid) {
    int sz = valid ? 16 : 0;
    asm volatile("cp.async.cg.shared.global [%0], [%1], 16, %2;\n"
                 :: "r"(dst), "l"(src), "r"(sz));
}
__device__ __forceinline__ void cp_commit() {
    asm volatile("cp.async.commit_group;\n" ::: "memory");
}
template <int N>
__device__ __forceinline__ void cp_wait() {
    asm volatile("cp.async.wait_group %0;\n" :: "n"(N) : "memory");
}
__device__ __forceinline__ void mma_tf32(float& c0, float& c1, float& c2, float& c3,
                                         uint32_t a0, uint32_t a1, uint32_t a2, uint32_t a3,
                                         uint32_t b0, uint32_t b1) {
    asm volatile(
        "mma.sync.aligned.m16n8k8.row.col.f32.tf32.tf32.f32 "
        "{%0,%1,%2,%3}, {%4,%5,%6,%7}, {%8,%9}, {%0,%1,%2,%3};"
        : "+f"(c0), "+f"(c1), "+f"(c2), "+f"(c3)
        : "r"(a0), "r"(a1), "r"(a2), "r"(a3), "r"(b0), "r"(b1));
}

// ---------------- init ----------------
__global__ void init_kernel() {
    int i = threadIdx.x;
    if (i < NEXP) { g_counts[i] = 0; g_fill[i] = 0; }
}

// ---------------- elementwise fp32 -> tf32(RN) convert ----------------
__global__ void cvt_kernel(const float* __restrict__ src, float* __restrict__ dst, int nvec4) {
    int i = blockIdx.x * blockDim.x + threadIdx.x;
    if (i >= nvec4) return;
    float4 v = ((const float4*)src)[i];
    v.x = f2tf32f(v.x); v.y = f2tf32f(v.y); v.z = f2tf32f(v.z); v.w = f2tf32f(v.w);
    ((float4*)dst)[i] = v;
}

// ---------------- router: top-2 + normalized weights ----------------
__global__ void router_kernel(const float* __restrict__ x,
                              const float* __restrict__ Wg, int T) {
    int warp = (blockIdx.x * blockDim.x + threadIdx.x) >> 5;
    int lane = threadIdx.x & 31;
    if (warp >= T) return;
    const float* xr = x + (size_t)warp * DDIM;
    float acc[NEXP];
    #pragma unroll
    for (int e = 0; e < NEXP; e++) acc[e] = 0.f;
    for (int d = lane; d < DDIM; d += 32) {
        float xv = xr[d];
        const float* wr = Wg + (size_t)d * NEXP;
        #pragma unroll
        for (int e = 0; e < NEXP; e++) acc[e] += xv * wr[e];
    }
    #pragma unroll
    for (int e = 0; e < NEXP; e++) {
        #pragma unroll
        for (int o = 16; o > 0; o >>= 1)
            acc[e] += __shfl_xor_sync(0xffffffffu, acc[e], o);
    }
    if (lane == 0) {
        int b0 = 0; float l0 = acc[0];
        #pragma unroll
        for (int e = 1; e < NEXP; e++)
            if (acc[e] > l0) { l0 = acc[e]; b0 = e; }
        int b1 = -1; float l1 = -3.0e38f;
        #pragma unroll
        for (int e = 0; e < NEXP; e++)
            if (e != b0 && acc[e] > l1) { l1 = acc[e]; b1 = e; }
        float w1 = 1.0f / (1.0f + expf(l0 - l1));
        float w0 = 1.0f - w1;
        g_e[2 * warp]     = b0;  g_e[2 * warp + 1]  = b1;
        g_wt[2 * warp]    = w0;  g_wt[2 * warp + 1] = w1;
        atomicAdd(&g_counts[b0], 1);
        atomicAdd(&g_counts[b1], 1);
    }
}

// ---------------- offsets ----------------
__global__ void offsets_kernel() {
    if (threadIdx.x == 0) {
        g_off[0] = 0;
        #pragma unroll
        for (int e = 0; e < NEXP; e++) {
            int c = g_counts[e];
            g_off[e + 1] = g_off[e] + ((c + BM - 1) / BM) * BM;
            g_fill[e] = 0;
        }
    }
}

// ---------------- scatter ----------------
__global__ void scatter_kernel(int T) {
    int t = blockIdx.x * blockDim.x + threadIdx.x;
    if (t >= T) return;
    #pragma unroll
    for (int k = 0; k < 2; k++) {
        int e   = g_e[2 * t + k];
        int pos = atomicAdd(&g_fill[e], 1);
        int slot = g_off[e] + pos;
        g_tok[slot]       = t;
        g_slot[2 * t + k] = slot;
    }
}

// ---------------- grouped GEMM (TF32 mma.sync, cp.async 3-stage pipeline) ----
// Operands are pre-rounded tf32 bits in global memory; no cvt in the hot loop.
// GATHER=true : A = g_xt gathered via g_tok, Out = g_h (tf32-rounded), +b, relu
// GATHER=false: A = g_h rows,                Out = g_y (fp32), +b
template <int KDIM, int NDIM, bool GATHER, bool RELU>
__global__ void __launch_bounds__(256, 2)
gemm_tc_kernel(const float* __restrict__ Asrc,
               const float* __restrict__ W,
               const float* __restrict__ bias) {
    extern __shared__ float smem[];
    float* AsBase = smem;                                  // [NSTAGE][BM*APITCH]
    float* BsBase = smem + NSTAGE * (BM * APITCH);         // [NSTAGE][BK*BPITCH]

    int r0 = blockIdx.y * BM;
    int n0 = blockIdx.x * BN;
    int totalRows = g_off[NEXP];
    if (r0 >= totalRows) return;

    int e = 0;
    #pragma unroll
    for (int i = 0; i < NEXP; i++)
        if (r0 >= g_off[i + 1]) e = i + 1;
    int cnt  = g_counts[e];
    int base = g_off[e];
    const float* Be = W + (size_t)e * KDIM * NDIM;

    int tid  = threadIdx.x;
    int wid  = tid >> 5;
    int lane = tid & 31;
    int g    = lane >> 2;
    int q    = lane & 3;
    int warpM = (wid >> 2) * 64;
    int warpN = (wid & 3) * 32;

    // A loader: row = tid>>1, 16 floats at (tid&1)*16
    int aRow = tid >> 1;
    int aCol = (tid & 1) * 16;
    bool aValid = true;
    const float* aP = nullptr;
    if (GATHER) {
        aValid = (unsigned)(r0 + aRow - base) < (unsigned)cnt;
        aP = Asrc + (aValid ? (size_t)g_tok[r0 + aRow] * KDIM : 0) + aCol;
    } else {
        aP = g_h + (size_t)(r0 + aRow) * KDIM + aCol;
    }
    // B loader: k-row = tid>>3, 16 floats at (tid&7)*16
    int bRow = tid >> 3;
    int bCol = (tid & 7) * 16;
    const float* bP = Be + (size_t)bRow * NDIM + n0 + bCol;

    uint32_t aDst0 = (uint32_t)__cvta_generic_to_shared(AsBase + aRow * APITCH + aCol);
    uint32_t bDst0 = (uint32_t)__cvta_generic_to_shared(BsBase + bRow * BPITCH + bCol);

    const int NT = KDIM / BK;   // k-tiles

    auto issue = [&](int t) {
        int s = t % NSTAGE;
        uint32_t aDst = aDst0 + s * (BM * APITCH) * 4;
        uint32_t bDst = bDst0 + s * (BK * BPITCH) * 4;
        int k0 = t * BK;
        #pragma unroll
        for (int j = 0; j < 4; j++)
            cp16(aDst + 16 * j, aP + k0 + 4 * j, aValid);
        #pragma unroll
        for (int j = 0; j < 4; j++)
            cp16(bDst + 16 * j, bP + (size_t)k0 * NDIM + 4 * j, true);
        cp_commit();
    };

    float acc[4][4][4];
    #pragma unroll
    for (int mf = 0; mf < 4; mf++)
        #pragma unroll
        for (int nf = 0; nf < 4; nf++)
            #pragma unroll
            for (int c = 0; c < 4; c++) acc[mf][nf][c] = 0.f;

    issue(0);
    issue(1);

    for (int t = 0; t < NT; t++) {
        int buf = t % NSTAGE;
        if (t + 1 < NT) cp_wait<1>(); else cp_wait<0>();
        __syncthreads();
        if (t + 2 < NT) issue(t + 2);

        const float* As = AsBase + buf * (BM * APITCH);
        const float* Bs = BsBase + buf * (BK * BPITCH);

        #pragma unroll
        for (int ks = 0; ks < 4; ks++) {
            int k8 = ks * 8;
            uint32_t afr[4][4], bfr[4][2];
            #pragma unroll
            for (int mf = 0; mf < 4; mf++) {
                int ab = (warpM + mf * 16 + g) * APITCH + k8 + q;
                afr[mf][0] = __float_as_uint(As[ab]);
                afr[mf][1] = __float_as_uint(As[ab + 8 * APITCH]);
                afr[mf][2] = __float_as_uint(As[ab + 4]);
                afr[mf][3] = __float_as_uint(As[ab + 8 * APITCH + 4]);
            }
            #pragma unroll
            for (int nf = 0; nf < 4; nf++) {
                int bb = (k8 + q) * BPITCH + warpN + nf * 8 + g;
                bfr[nf][0] = __float_as_uint(Bs[bb]);
                bfr[nf][1] = __float_as_uint(Bs[bb + 4 * BPITCH]);
            }
            #pragma unroll
            for (int mf = 0; mf < 4; mf++)
                #pragma unroll
                for (int nf = 0; nf < 4; nf++)
                    mma_tf32(acc[mf][nf][0], acc[mf][nf][1],
                             acc[mf][nf][2], acc[mf][nf][3],
                             afr[mf][0], afr[mf][1], afr[mf][2], afr[mf][3],
                             bfr[nf][0], bfr[nf][1]);
        }
        __syncthreads();
    }

    // ---- epilogue ----
    const float* be = bias + (size_t)e * NDIM;
    float* OutBuf = GATHER ? g_h : g_y;
    #pragma unroll
    for (int mf = 0; mf < 4; mf++) {
        int row0 = r0 + warpM + mf * 16 + g;
        int row1 = row0 + 8;
        #pragma unroll
        for (int nf = 0; nf < 4; nf++) {
            int col = n0 + warpN + nf * 8 + q * 2;
            float bv0 = be[col], bv1 = be[col + 1];
            float2 v0, v1;
            v0.x = acc[mf][nf][0] + bv0;  v0.y = acc[mf][nf][1] + bv1;
            v1.x = acc[mf][nf][2] + bv0;  v1.y = acc[mf][nf][3] + bv1;
            if (RELU) {
                v0.x = fmaxf(v0.x, 0.f); v0.y = fmaxf(v0.y, 0.f);
                v1.x = fmaxf(v1.x, 0.f); v1.y = fmaxf(v1.y, 0.f);
            }
            if (GATHER) {   // next GEMM consumes as tf32: round now
                v0.x = f2tf32f(v0.x); v0.y = f2tf32f(v0.y);
                v1.x = f2tf32f(v1.x); v1.y = f2tf32f(v1.y);
            }
            *(float2*)(OutBuf + (size_t)row0 * NDIM + col) = v0;
            *(float2*)(OutBuf + (size_t)row1 * NDIM + col) = v1;
        }
    }
}

// ---------------- combine ----------------
__global__ void combine_kernel(float* __restrict__ out, int T) {
    int i = blockIdx.x * blockDim.x + threadIdx.x;
    int nvec = T * (DDIM / 4);
    if (i >= nvec) return;
    int t = i / (DDIM / 4);
    int j = i % (DDIM / 4);
    int s0 = g_slot[2 * t], s1 = g_slot[2 * t + 1];
    float w0 = g_wt[2 * t], w1 = g_wt[2 * t + 1];
    float4 y0 = ((const float4*)(g_y + (size_t)s0 * DDIM))[j];
    float4 y1 = ((const float4*)(g_y + (size_t)s1 * DDIM))[j];
    float4 o;
    o.x = w0 * y0.x + w1 * y1.x;
    o.y = w0 * y0.y + w1 * y1.y;
    o.z = w0 * y0.z + w1 * y1.z;
    o.w = w0 * y0.w + w1 * y1.w;
    ((float4*)out)[i] = o;
}

// ---------------- launch ----------------
extern "C" void kernel_launch(void* const* d_in, const int* in_sizes, int n_in,
                              void* d_out, int out_size) {
    const float* x  = (const float*)d_in[0];
    const float* Wg = (const float*)d_in[1];
    const float* W1 = (const float*)d_in[2];
    const float* b1 = (const float*)d_in[3];
    const float* W2 = (const float*)d_in[4];
    const float* b2 = (const float*)d_in[5];
    float* out = (float*)d_out;
    int T = in_sizes[0] / DDIM;   // 8192

    static float* s_xt  = nullptr;
    static float* s_w1t = nullptr;
    static float* s_w2t = nullptr;
    if (!s_xt) {
        cudaGetSymbolAddress((void**)&s_xt,  g_xt);
        cudaGetSymbolAddress((void**)&s_w1t, g_w1t);
        cudaGetSymbolAddress((void**)&s_w2t, g_w2t);
        cudaFuncSetAttribute(gemm_tc_kernel<DDIM, HDIM, true,  true >,
                             cudaFuncAttributeMaxDynamicSharedMemorySize, SMEM_GEMM);
        cudaFuncSetAttribute(gemm_tc_kernel<HDIM, DDIM, false, false>,
                             cudaFuncAttributeMaxDynamicSharedMemorySize, SMEM_GEMM);
    }

    init_kernel<<<1, 32>>>();

    // pre-convert operands to tf32 (RN)
    int nx  = T * DDIM / 4;
    int nw1 = NEXP * DDIM * HDIM / 4;
    int nw2 = NEXP * HDIM * DDIM / 4;
    cvt_kernel<<<(nx  + 255) / 256, 256>>>(x,  s_xt,  nx);
    cvt_kernel<<<(nw1 + 255) / 256, 256>>>(W1, s_w1t, nw1);
    cvt_kernel<<<(nw2 + 255) / 256, 256>>>(W2, s_w2t, nw2);

    router_kernel<<<(T + 7) / 8, 256>>>(x, Wg, T);
    offsets_kernel<<<1, 32>>>();
    scatter_kernel<<<(T + 255) / 256, 256>>>(T);

    dim3 grid1(HDIM / BN, SLOT_MAX / BM);
    gemm_tc_kernel<DDIM, HDIM, true,  true ><<<grid1, 256, SMEM_GEMM>>>(s_xt, s_w1t, b1);

    dim3 grid2(DDIM / BN, SLOT_MAX / BM);
    gemm_tc_kernel<HDIM, DDIM, false, false><<<grid2, 256, SMEM_GEMM>>>(nullptr, s_w2t, b2);

    int nvec = T * (DDIM / 4);
    combine_kernel<<<(nvec + 255) / 256, 256>>>(out, T);
}

// round 8
// speedup vs baseline: 2.9188x; 2.9188x over previous
#include <cuda_runtime.h>
#include <cuda_fp16.h>
#include <cstdint>

// ---------------- problem constants ----------------
#define NEXP   8
#define DDIM   1024
#define HDIM   2048
#define TMAX   8192
#define BM     128
#define BN     128
#define BK     32            // k-halves per pipeline stage (64 B/row)
#define SLOT_MAX (2*TMAX + NEXP*BM)   // 17408
#define NSTAGE 3
#define PW     20            // smem row pitch in 32-bit words (16 data + 4 pad)
#define TILE_WORDS (BM * PW)          // 2560 words per tile
#define STG_WORDS  (2 * TILE_WORDS)   // A + B per stage
#define SMEM_GEMM  (NSTAGE * STG_WORDS * 4)   // 61440 B

// ---------------- device scratch ----------------
__device__ int    g_counts[NEXP];
__device__ int    g_fill[NEXP];
__device__ int    g_off[NEXP + 1];
__device__ int    g_tok[SLOT_MAX];
__device__ int    g_slot[2 * TMAX];
__device__ int    g_e[2 * TMAX];
__device__ float  g_wt[2 * TMAX];
__device__ __half g_h[(size_t)SLOT_MAX * HDIM];      // fp16 hidden acts
__device__ float  g_y[(size_t)SLOT_MAX * DDIM];      // fp32 expert outputs
__device__ __half g_xh[(size_t)TMAX * DDIM];         // fp16 x
__device__ __half g_w1t[(size_t)NEXP * HDIM * DDIM]; // W1^T [E][H][D] fp16
__device__ __half g_w2t[(size_t)NEXP * DDIM * HDIM]; // W2^T [E][D][H] fp16

// ---------------- helpers ----------------
__device__ __forceinline__ void cp16(uint32_t dst, const void* src, bool valid) {
    int sz = valid ? 16 : 0;
    asm volatile("cp.async.cg.shared.global [%0], [%1], 16, %2;\n"
                 :: "r"(dst), "l"(src), "r"(sz));
}
__device__ __forceinline__ void cp_commit() {
    asm volatile("cp.async.commit_group;\n" ::: "memory");
}
template <int N>
__device__ __forceinline__ void cp_wait() {
    asm volatile("cp.async.wait_group %0;\n" :: "n"(N) : "memory");
}
__device__ __forceinline__ void mma_f16(float& c0, float& c1, float& c2, float& c3,
                                        uint32_t a0, uint32_t a1, uint32_t a2, uint32_t a3,
                                        uint32_t b0, uint32_t b1) {
    asm volatile(
        "mma.sync.aligned.m16n8k16.row.col.f32.f16.f16.f32 "
        "{%0,%1,%2,%3}, {%4,%5,%6,%7}, {%8,%9}, {%0,%1,%2,%3};"
        : "+f"(c0), "+f"(c1), "+f"(c2), "+f"(c3)
        : "r"(a0), "r"(a1), "r"(a2), "r"(a3), "r"(b0), "r"(b1));
}

// ---------------- init ----------------
__global__ void init_kernel() {
    int i = threadIdx.x;
    if (i < NEXP) { g_counts[i] = 0; g_fill[i] = 0; }
}

// ---------------- fp32 -> fp16 elementwise ----------------
__global__ void cvt_h_kernel(const float* __restrict__ src, __half* __restrict__ dst, int nvec4) {
    int i = blockIdx.x * blockDim.x + threadIdx.x;
    if (i >= nvec4) return;
    float4 v = ((const float4*)src)[i];
    __half2 h0 = __floats2half2_rn(v.x, v.y);
    __half2 h1 = __floats2half2_rn(v.z, v.w);
    ((__half2*)dst)[2 * i]     = h0;
    ((__half2*)dst)[2 * i + 1] = h1;
}

// ---------------- W[e][K][N] fp32 -> Wt[e][N][K] fp16 ----------------
__global__ void transpose_h_kernel(const float* __restrict__ src, __half* __restrict__ dst,
                                   int K, int N) {
    __shared__ float t[32][33];
    int e = blockIdx.z;
    const float* s = src + (size_t)e * K * N;
    __half* d = dst + (size_t)e * N * K;
    int k0 = blockIdx.x * 32, n0 = blockIdx.y * 32;
    int x = threadIdx.x, y = threadIdx.y;   // 32 x 8
    #pragma unroll
    for (int i = 0; i < 32; i += 8)
        t[y + i][x] = s[(size_t)(k0 + y + i) * N + (n0 + x)];
    __syncthreads();
    #pragma unroll
    for (int i = 0; i < 32; i += 8)
        d[(size_t)(n0 + y + i) * K + (k0 + x)] = __float2half_rn(t[x][y + i]);
}

// ---------------- router: top-2 + normalized weights ----------------
__global__ void router_kernel(const float* __restrict__ x,
                              const float* __restrict__ Wg, int T) {
    int warp = (blockIdx.x * blockDim.x + threadIdx.x) >> 5;
    int lane = threadIdx.x & 31;
    if (warp >= T) return;
    const float* xr = x + (size_t)warp * DDIM;
    float acc[NEXP];
    #pragma unroll
    for (int e = 0; e < NEXP; e++) acc[e] = 0.f;
    for (int d = lane; d < DDIM; d += 32) {
        float xv = xr[d];
        const float* wr = Wg + (size_t)d * NEXP;
        #pragma unroll
        for (int e = 0; e < NEXP; e++) acc[e] += xv * wr[e];
    }
    #pragma unroll
    for (int e = 0; e < NEXP; e++) {
        #pragma unroll
        for (int o = 16; o > 0; o >>= 1)
            acc[e] += __shfl_xor_sync(0xffffffffu, acc[e], o);
    }
    if (lane == 0) {
        int b0 = 0; float l0 = acc[0];
        #pragma unroll
        for (int e = 1; e < NEXP; e++)
            if (acc[e] > l0) { l0 = acc[e]; b0 = e; }
        int b1 = -1; float l1 = -3.0e38f;
        #pragma unroll
        for (int e = 0; e < NEXP; e++)
            if (e != b0 && acc[e] > l1) { l1 = acc[e]; b1 = e; }
        float w1 = 1.0f / (1.0f + expf(l0 - l1));
        float w0 = 1.0f - w1;
        g_e[2 * warp]     = b0;  g_e[2 * warp + 1]  = b1;
        g_wt[2 * warp]    = w0;  g_wt[2 * warp + 1] = w1;
        atomicAdd(&g_counts[b0], 1);
        atomicAdd(&g_counts[b1], 1);
    }
}

// ---------------- offsets ----------------
__global__ void offsets_kernel() {
    if (threadIdx.x == 0) {
        g_off[0] = 0;
        #pragma unroll
        for (int e = 0; e < NEXP; e++) {
            int c = g_counts[e];
            g_off[e + 1] = g_off[e] + ((c + BM - 1) / BM) * BM;
            g_fill[e] = 0;
        }
    }
}

// ---------------- scatter ----------------
__global__ void scatter_kernel(int T) {
    int t = blockIdx.x * blockDim.x + threadIdx.x;
    if (t >= T) return;
    #pragma unroll
    for (int k = 0; k < 2; k++) {
        int e   = g_e[2 * t + k];
        int pos = atomicAdd(&g_fill[e], 1);
        int slot = g_off[e] + pos;
        g_tok[slot]       = t;
        g_slot[2 * t + k] = slot;
    }
}

// ---------------- grouped GEMM: fp16 mma.sync, 128x128x32, 3-stage cp.async ----
// A tile [BM][BK] halves k-contiguous; B tile = Wt rows [BN][BK] halves (B^T).
// GATHER=true : A = g_xh via g_tok, Out = g_h (fp16), +b, relu
// GATHER=false: A = g_h rows,       Out = g_y (fp32), +b
template <int KDIM, int NDIM, bool GATHER, bool RELU>
__global__ void __launch_bounds__(256, 2)
gemm_f16(const __half* __restrict__ Asrc,
         const __half* __restrict__ Wt,     // [E][NDIM][KDIM] fp16
         const float* __restrict__ bias) {  // [E][NDIM]
    extern __shared__ uint32_t smw[];

    int r0 = blockIdx.y * BM;
    int totalRows = g_off[NEXP];
    if (r0 >= totalRows) return;
    int n0 = blockIdx.x * BN;

    int e = 0;
    #pragma unroll
    for (int i = 0; i < NEXP; i++)
        if (r0 >= g_off[i + 1]) e = i + 1;
    int cnt = g_counts[e], base = g_off[e];

    int tid  = threadIdx.x;
    int wid  = tid >> 5;
    int lane = tid & 31;
    int g    = lane >> 2;
    int q    = lane & 3;
    int warpM = (wid >> 2) * 64;   // 0 / 64
    int warpN = (wid & 3) * 32;    // 0..96

    // ---- loaders: thread -> row = tid>>1, two 16B chunks at (tid&1)*32B ----
    int row  = tid >> 1;
    int half0 = (tid & 1) * 16;    // half-element offset within the 32-half row
    const __half* aRowP;
    bool aValid = true;
    if (GATHER) {
        int slot = r0 + row;
        aValid = (unsigned)(slot - base) < (unsigned)cnt;
        aRowP = Asrc + (size_t)(aValid ? g_tok[slot] : 0) * KDIM + half0;
    } else {
        aRowP = g_h + (size_t)(r0 + row) * KDIM + half0;
    }
    const __half* bRowP = Wt + (size_t)e * NDIM * KDIM + (size_t)(n0 + row) * KDIM + half0;

    uint32_t smem_base = (uint32_t)__cvta_generic_to_shared(smw);
    uint32_t aOff = smem_base + (row * PW + (tid & 1) * 8) * 4;   // byte addr
    uint32_t bOff = aOff + TILE_WORDS * 4;

    auto issue = [&](int t) {
        int s = t % NSTAGE;
        uint32_t sb = s * (STG_WORDS * 4);
        int k0 = t * BK;
        cp16(aOff + sb,      aRowP + k0, aValid);
        cp16(aOff + sb + 16, aRowP + k0 + 8, aValid);
        cp16(bOff + sb,      bRowP + k0, true);
        cp16(bOff + sb + 16, bRowP + k0 + 8, true);
        cp_commit();
    };

    float acc[4][4][4];
    #pragma unroll
    for (int mf = 0; mf < 4; mf++)
        #pragma unroll
        for (int nf = 0; nf < 4; nf++)
            #pragma unroll
            for (int c = 0; c < 4; c++) acc[mf][nf][c] = 0.f;

    const int NT = KDIM / BK;
    issue(0); issue(1);

    for (int t = 0; t < NT; t++) {
        int s = t % NSTAGE;
        if (t + 1 < NT) cp_wait<1>(); else cp_wait<0>();
        __syncthreads();                 // orders buffer reuse + data visibility
        if (t + 2 < NT) issue(t + 2);

        const uint32_t* As = smw + s * STG_WORDS;
        const uint32_t* Bs = As + TILE_WORDS;

        #pragma unroll
        for (int ks = 0; ks < 2; ks++) {
            int kw = ks * 8;             // word offset of this k16 step
            uint32_t afr[4][4], bfr[4][2];
            #pragma unroll
            for (int mf = 0; mf < 4; mf++) {
                int aw = (warpM + mf * 16 + g) * PW + kw + q;
                afr[mf][0] = As[aw];
                afr[mf][1] = As[aw + 8 * PW];
                afr[mf][2] = As[aw + 4];
                afr[mf][3] = As[aw + 8 * PW + 4];
            }
            #pragma unroll
            for (int nf = 0; nf < 4; nf++) {
                int bw = (warpN + nf * 8 + g) * PW + kw + q;
                bfr[nf][0] = Bs[bw];
                bfr[nf][1] = Bs[bw + 4];
            }
            #pragma unroll
            for (int mf = 0; mf < 4; mf++)
                #pragma unroll
                for (int nf = 0; nf < 4; nf++)
                    mma_f16(acc[mf][nf][0], acc[mf][nf][1],
                            acc[mf][nf][2], acc[mf][nf][3],
                            afr[mf][0], afr[mf][1], afr[mf][2], afr[mf][3],
                            bfr[nf][0], bfr[nf][1]);
        }
    }

    // ---- epilogue: bias (+relu) ----
    const float* be = bias + (size_t)e * NDIM;
    #pragma unroll
    for (int mf = 0; mf < 4; mf++) {
        int row0 = r0 + warpM + mf * 16 + g;
        int row1 = row0 + 8;
        #pragma unroll
        for (int nf = 0; nf < 4; nf++) {
            int col = n0 + warpN + nf * 8 + q * 2;
            float bv0 = be[col], bv1 = be[col + 1];
            float v00 = acc[mf][nf][0] + bv0, v01 = acc[mf][nf][1] + bv1;
            float v10 = acc[mf][nf][2] + bv0, v11 = acc[mf][nf][3] + bv1;
            if (RELU) {
                v00 = fmaxf(v00, 0.f); v01 = fmaxf(v01, 0.f);
                v10 = fmaxf(v10, 0.f); v11 = fmaxf(v11, 0.f);
            }
            if (GATHER) {
                *(__half2*)(g_h + (size_t)row0 * NDIM + col) = __floats2half2_rn(v00, v01);
                *(__half2*)(g_h + (size_t)row1 * NDIM + col) = __floats2half2_rn(v10, v11);
            } else {
                *(float2*)(g_y + (size_t)row0 * NDIM + col) = make_float2(v00, v01);
                *(float2*)(g_y + (size_t)row1 * NDIM + col) = make_float2(v10, v11);
            }
        }
    }
}

// ---------------- combine ----------------
__global__ void combine_kernel(float* __restrict__ out, int T) {
    int i = blockIdx.x * blockDim.x + threadIdx.x;
    int nvec = T * (DDIM / 4);
    if (i >= nvec) return;
    int t = i / (DDIM / 4);
    int j = i % (DDIM / 4);
    int s0 = g_slot[2 * t], s1 = g_slot[2 * t + 1];
    float w0 = g_wt[2 * t], w1 = g_wt[2 * t + 1];
    float4 y0 = ((const float4*)(g_y + (size_t)s0 * DDIM))[j];
    float4 y1 = ((const float4*)(g_y + (size_t)s1 * DDIM))[j];
    float4 o;
    o.x = w0 * y0.x + w1 * y1.x;
    o.y = w0 * y0.y + w1 * y1.y;
    o.z = w0 * y0.z + w1 * y1.z;
    o.w = w0 * y0.w + w1 * y1.w;
    ((float4*)out)[i] = o;
}

// ---------------- launch ----------------
extern "C" void kernel_launch(void* const* d_in, const int* in_sizes, int n_in,
                              void* d_out, int out_size) {
    const float* x  = (const float*)d_in[0];
    const float* Wg = (const float*)d_in[1];
    const float* W1 = (const float*)d_in[2];
    const float* b1 = (const float*)d_in[3];
    const float* W2 = (const float*)d_in[4];
    const float* b2 = (const float*)d_in[5];
    float* out = (float*)d_out;
    int T = in_sizes[0] / DDIM;   // 8192

    __half *s_xh, *s_w1t, *s_w2t;
    cudaGetSymbolAddress((void**)&s_xh,  g_xh);
    cudaGetSymbolAddress((void**)&s_w1t, g_w1t);
    cudaGetSymbolAddress((void**)&s_w2t, g_w2t);
    cudaFuncSetAttribute(gemm_f16<DDIM, HDIM, true,  true >,
                         cudaFuncAttributeMaxDynamicSharedMemorySize, SMEM_GEMM);
    cudaFuncSetAttribute(gemm_f16<HDIM, DDIM, false, false>,
                         cudaFuncAttributeMaxDynamicSharedMemorySize, SMEM_GEMM);

    init_kernel<<<1, 32>>>();

    // preprocessing: x -> fp16, W -> transposed fp16
    int nx = T * DDIM / 4;
    cvt_h_kernel<<<(nx + 255) / 256, 256>>>(x, s_xh, nx);
    dim3 tb(32, 8);
    transpose_h_kernel<<<dim3(DDIM / 32, HDIM / 32, NEXP), tb>>>(W1, s_w1t, DDIM, HDIM);
    transpose_h_kernel<<<dim3(HDIM / 32, DDIM / 32, NEXP), tb>>>(W2, s_w2t, HDIM, DDIM);

    router_kernel<<<(T + 7) / 8, 256>>>(x, Wg, T);
    offsets_kernel<<<1, 32>>>();
    scatter_kernel<<<(T + 255) / 256, 256>>>(T);

    dim3 grid1(HDIM / BN, SLOT_MAX / BM);   // 16 x 136
    gemm_f16<DDIM, HDIM, true,  true ><<<grid1, 256, SMEM_GEMM>>>(s_xh, s_w1t, b1);

    dim3 grid2(DDIM / BN, SLOT_MAX / BM);   // 8 x 136
    gemm_f16<HDIM, DDIM, false, false><<<grid2, 256, SMEM_GEMM>>>(nullptr, s_w2t, b2);

    int nvec = T * (DDIM / 4);
    combine_kernel<<<(nvec + 255) / 256, 256>>>(out, T);
}

// round 9
// speedup vs baseline: 2.9274x; 1.0029x over previous
#include <cuda_runtime.h>
#include <cuda_fp16.h>
#include <cstdint>

// ---------------- problem constants ----------------
#define NEXP   8
#define DDIM   1024
#define HDIM   2048
#define TMAX   8192
#define BM     128
#define BN     256
#define BK     32            // k-halves per stage (64 B/row)
#define SLOT_MAX (2*TMAX + NEXP*BM)   // 17408
#define NSTAGE 3
#define ROWB   80            // smem row pitch bytes (64 data + 16 pad)
#define ASTG   (BM * ROWB)   // 10240 B
#define BSTG   (BN * ROWB)   // 20480 B
#define STGB   (ASTG + BSTG) // 30720 B
#define SMEM_GEMM (NSTAGE * STGB)     // 92160 B

// ---------------- device scratch ----------------
__device__ int    g_counts[NEXP];
__device__ int    g_fill[NEXP];
__device__ int    g_off[NEXP + 1];
__device__ int    g_tok[SLOT_MAX];
__device__ int    g_slot[2 * TMAX];
__device__ int    g_e[2 * TMAX];
__device__ float  g_wt[2 * TMAX];
__device__ __half g_h[(size_t)SLOT_MAX * HDIM];      // fp16 hidden acts
__device__ float  g_y[(size_t)SLOT_MAX * DDIM];      // fp32 expert outputs
__device__ __half g_xh[(size_t)TMAX * DDIM];         // fp16 x
__device__ __half g_w1t[(size_t)NEXP * HDIM * DDIM]; // W1^T [E][H][D] fp16
__device__ __half g_w2t[(size_t)NEXP * DDIM * HDIM]; // W2^T [E][D][H] fp16

// ---------------- helpers ----------------
__device__ __forceinline__ void cp16(uint32_t dst, const void* src, bool valid) {
    int sz = valid ? 16 : 0;
    asm volatile("cp.async.cg.shared.global [%0], [%1], 16, %2;\n"
                 :: "r"(dst), "l"(src), "r"(sz));
}
__device__ __forceinline__ void cp_commit() {
    asm volatile("cp.async.commit_group;\n" ::: "memory");
}
template <int N>
__device__ __forceinline__ void cp_wait() {
    asm volatile("cp.async.wait_group %0;\n" :: "n"(N) : "memory");
}
__device__ __forceinline__ void ldsm4(uint32_t& r0, uint32_t& r1, uint32_t& r2, uint32_t& r3,
                                      uint32_t addr) {
    asm volatile("ldmatrix.sync.aligned.m8n8.x4.shared.b16 {%0,%1,%2,%3}, [%4];"
                 : "=r"(r0), "=r"(r1), "=r"(r2), "=r"(r3) : "r"(addr));
}
__device__ __forceinline__ void mma_f16(float& c0, float& c1, float& c2, float& c3,
                                        uint32_t a0, uint32_t a1, uint32_t a2, uint32_t a3,
                                        uint32_t b0, uint32_t b1) {
    asm volatile(
        "mma.sync.aligned.m16n8k16.row.col.f32.f16.f16.f32 "
        "{%0,%1,%2,%3}, {%4,%5,%6,%7}, {%8,%9}, {%0,%1,%2,%3};"
        : "+f"(c0), "+f"(c1), "+f"(c2), "+f"(c3)
        : "r"(a0), "r"(a1), "r"(a2), "r"(a3), "r"(b0), "r"(b1));
}

// ---------------- init ----------------
__global__ void init_kernel() {
    int i = threadIdx.x;
    if (i < NEXP) { g_counts[i] = 0; g_fill[i] = 0; }
}

// ---------------- fp32 -> fp16 elementwise ----------------
__global__ void cvt_h_kernel(const float* __restrict__ src, __half* __restrict__ dst, int nvec4) {
    int i = blockIdx.x * blockDim.x + threadIdx.x;
    if (i >= nvec4) return;
    float4 v = ((const float4*)src)[i];
    ((__half2*)dst)[2 * i]     = __floats2half2_rn(v.x, v.y);
    ((__half2*)dst)[2 * i + 1] = __floats2half2_rn(v.z, v.w);
}

// ---------------- W[e][K][N] fp32 -> Wt[e][N][K] fp16 ----------------
__global__ void transpose_h_kernel(const float* __restrict__ src, __half* __restrict__ dst,
                                   int K, int N) {
    __shared__ float t[32][33];
    int e = blockIdx.z;
    const float* s = src + (size_t)e * K * N;
    __half* d = dst + (size_t)e * N * K;
    int k0 = blockIdx.x * 32, n0 = blockIdx.y * 32;
    int x = threadIdx.x, y = threadIdx.y;   // 32 x 8
    #pragma unroll
    for (int i = 0; i < 32; i += 8)
        t[y + i][x] = s[(size_t)(k0 + y + i) * N + (n0 + x)];
    __syncthreads();
    #pragma unroll
    for (int i = 0; i < 32; i += 8)
        d[(size_t)(n0 + y + i) * K + (k0 + x)] = __float2half_rn(t[x][y + i]);
}

// ---------------- router: top-2 + normalized weights ----------------
__global__ void router_kernel(const float* __restrict__ x,
                              const float* __restrict__ Wg, int T) {
    int warp = (blockIdx.x * blockDim.x + threadIdx.x) >> 5;
    int lane = threadIdx.x & 31;
    if (warp >= T) return;
    const float* xr = x + (size_t)warp * DDIM;
    float acc[NEXP];
    #pragma unroll
    for (int e = 0; e < NEXP; e++) acc[e] = 0.f;
    for (int d = lane; d < DDIM; d += 32) {
        float xv = xr[d];
        const float* wr = Wg + (size_t)d * NEXP;
        #pragma unroll
        for (int e = 0; e < NEXP; e++) acc[e] += xv * wr[e];
    }
    #pragma unroll
    for (int e = 0; e < NEXP; e++) {
        #pragma unroll
        for (int o = 16; o > 0; o >>= 1)
            acc[e] += __shfl_xor_sync(0xffffffffu, acc[e], o);
    }
    if (lane == 0) {
        int b0 = 0; float l0 = acc[0];
        #pragma unroll
        for (int e = 1; e < NEXP; e++)
            if (acc[e] > l0) { l0 = acc[e]; b0 = e; }
        int b1 = -1; float l1 = -3.0e38f;
        #pragma unroll
        for (int e = 0; e < NEXP; e++)
            if (e != b0 && acc[e] > l1) { l1 = acc[e]; b1 = e; }
        float w1 = 1.0f / (1.0f + expf(l0 - l1));
        float w0 = 1.0f - w1;
        g_e[2 * warp]     = b0;  g_e[2 * warp + 1]  = b1;
        g_wt[2 * warp]    = w0;  g_wt[2 * warp + 1] = w1;
        atomicAdd(&g_counts[b0], 1);
        atomicAdd(&g_counts[b1], 1);
    }
}

// ---------------- offsets ----------------
__global__ void offsets_kernel() {
    if (threadIdx.x == 0) {
        g_off[0] = 0;
        #pragma unroll
        for (int e = 0; e < NEXP; e++) {
            int c = g_counts[e];
            g_off[e + 1] = g_off[e] + ((c + BM - 1) / BM) * BM;
            g_fill[e] = 0;
        }
    }
}

// ---------------- scatter ----------------
__global__ void scatter_kernel(int T) {
    int t = blockIdx.x * blockDim.x + threadIdx.x;
    if (t >= T) return;
    #pragma unroll
    for (int k = 0; k < 2; k++) {
        int e   = g_e[2 * t + k];
        int pos = atomicAdd(&g_fill[e], 1);
        int slot = g_off[e] + pos;
        g_tok[slot]       = t;
        g_slot[2 * t + k] = slot;
    }
}

// ---------------- grouped GEMM: fp16 mma + ldmatrix, 128x256 tile, 512 thr ---
// 16 warps in 4(m) x 4(n): warp tile 32x64. 3-stage cp.async ring.
// GATHER=true : A = g_xh via g_tok, Out = g_h (fp16), +b, relu
// GATHER=false: A = g_h rows,       Out = g_y (fp32), +b
template <int KDIM, int NDIM, bool GATHER, bool RELU>
__global__ void __launch_bounds__(512, 1)
gemm_f16(const __half* __restrict__ Asrc,
         const __half* __restrict__ Wt,     // [E][NDIM][KDIM] fp16
         const float* __restrict__ bias) {  // [E][NDIM]
    extern __shared__ uint8_t smb[];

    int r0 = blockIdx.y * BM;
    int totalRows = g_off[NEXP];
    if (r0 >= totalRows) return;
    int n0 = blockIdx.x * BN;

    int e = 0;
    #pragma unroll
    for (int i = 0; i < NEXP; i++)
        if (r0 >= g_off[i + 1]) e = i + 1;
    int cnt = g_counts[e], base = g_off[e];

    int tid  = threadIdx.x;
    int wid  = tid >> 5;
    int lane = tid & 31;
    int g    = lane >> 2;
    int q    = lane & 3;
    int warpM = (wid & 3) * 32;    // 0,32,64,96
    int warpN = (wid >> 2) * 64;   // 0,64,128,192

    uint32_t smem_base = (uint32_t)__cvta_generic_to_shared(smb);

    // ---- loaders ----
    // A: 128 rows x 4 chunks(16B) = 512 -> 1 per thread
    int aLrow = tid >> 2, aLc = tid & 3;
    const __half* aRowP;
    bool aValid = true;
    if (GATHER) {
        int slot = r0 + aLrow;
        aValid = (unsigned)(slot - base) < (unsigned)cnt;
        aRowP = Asrc + (size_t)(aValid ? g_tok[slot] : 0) * KDIM + aLc * 8;
    } else {
        aRowP = g_h + (size_t)(r0 + aLrow) * KDIM + aLc * 8;
    }
    uint32_t aDst = smem_base + aLrow * ROWB + aLc * 16;
    // B: 256 rows x 4 chunks = 1024 -> 2 per thread (one row, 2 chunks)
    int bLrow = tid >> 1, bLc = (tid & 1) * 2;
    const __half* bRowP = Wt + (size_t)e * NDIM * KDIM + (size_t)(n0 + bLrow) * KDIM + bLc * 8;
    uint32_t bDst = smem_base + ASTG + bLrow * ROWB + bLc * 16;

    auto issue = [&](int t) {
        uint32_t sb = (t % NSTAGE) * STGB;
        int k0 = t * BK;
        cp16(aDst + sb, aRowP + k0, aValid);
        cp16(bDst + sb,      bRowP + k0, true);
        cp16(bDst + sb + 16, bRowP + k0 + 8, true);
        cp_commit();
    };

    // ---- ldmatrix lane addressing ----
    int arow = (lane & 7) | ((lane >> 3) & 1) << 3;    // 0..15
    int aksel = (lane >> 4) & 1;                       // k8 select
    uint32_t aFrag = smem_base + (warpM + arow) * ROWB + aksel * 16;
    int brow = (lane & 7) | ((lane >> 4) & 1) << 3;    // 0..15
    int bksel = (lane >> 3) & 1;
    uint32_t bFrag = smem_base + ASTG + (warpN + brow) * ROWB + bksel * 16;

    float acc[2][8][4];
    #pragma unroll
    for (int mf = 0; mf < 2; mf++)
        #pragma unroll
        for (int nf = 0; nf < 8; nf++)
            #pragma unroll
            for (int c = 0; c < 4; c++) acc[mf][nf][c] = 0.f;

    const int NT = KDIM / BK;
    issue(0); issue(1);

    for (int t = 0; t < NT; t++) {
        uint32_t sb = (t % NSTAGE) * STGB;
        if (t + 1 < NT) cp_wait<1>(); else cp_wait<0>();
        __syncthreads();
        if (t + 2 < NT) issue(t + 2);

        #pragma unroll
        for (int ks = 0; ks < 2; ks++) {
            uint32_t ko = ks * 32;     // 16 halves = 32 B
            uint32_t afr[2][4], bfr[4][4];
            #pragma unroll
            for (int mf = 0; mf < 2; mf++)
                ldsm4(afr[mf][0], afr[mf][1], afr[mf][2], afr[mf][3],
                      aFrag + sb + mf * 16 * ROWB + ko);
            #pragma unroll
            for (int nh = 0; nh < 4; nh++)
                ldsm4(bfr[nh][0], bfr[nh][1], bfr[nh][2], bfr[nh][3],
                      bFrag + sb + nh * 16 * ROWB + ko);
            #pragma unroll
            for (int mf = 0; mf < 2; mf++)
                #pragma unroll
                for (int nh = 0; nh < 4; nh++) {
                    mma_f16(acc[mf][2*nh][0], acc[mf][2*nh][1],
                            acc[mf][2*nh][2], acc[mf][2*nh][3],
                            afr[mf][0], afr[mf][1], afr[mf][2], afr[mf][3],
                            bfr[nh][0], bfr[nh][1]);
                    mma_f16(acc[mf][2*nh+1][0], acc[mf][2*nh+1][1],
                            acc[mf][2*nh+1][2], acc[mf][2*nh+1][3],
                            afr[mf][0], afr[mf][1], afr[mf][2], afr[mf][3],
                            bfr[nh][2], bfr[nh][3]);
                }
        }
    }

    // ---- epilogue: bias (+relu) ----
    const float* be = bias + (size_t)e * NDIM;
    #pragma unroll
    for (int mf = 0; mf < 2; mf++) {
        int row0 = r0 + warpM + mf * 16 + g;
        int row1 = row0 + 8;
        #pragma unroll
        for (int nf = 0; nf < 8; nf++) {
            int col = n0 + warpN + nf * 8 + q * 2;
            float bv0 = be[col], bv1 = be[col + 1];
            float v00 = acc[mf][nf][0] + bv0, v01 = acc[mf][nf][1] + bv1;
            float v10 = acc[mf][nf][2] + bv0, v11 = acc[mf][nf][3] + bv1;
            if (RELU) {
                v00 = fmaxf(v00, 0.f); v01 = fmaxf(v01, 0.f);
                v10 = fmaxf(v10, 0.f); v11 = fmaxf(v11, 0.f);
            }
            if (GATHER) {
                *(__half2*)(g_h + (size_t)row0 * NDIM + col) = __floats2half2_rn(v00, v01);
                *(__half2*)(g_h + (size_t)row1 * NDIM + col) = __floats2half2_rn(v10, v11);
            } else {
                *(float2*)(g_y + (size_t)row0 * NDIM + col) = make_float2(v00, v01);
                *(float2*)(g_y + (size_t)row1 * NDIM + col) = make_float2(v10, v11);
            }
        }
    }
}

// ---------------- combine ----------------
__global__ void combine_kernel(float* __restrict__ out, int T) {
    int i = blockIdx.x * blockDim.x + threadIdx.x;
    int nvec = T * (DDIM / 4);
    if (i >= nvec) return;
    int t = i / (DDIM / 4);
    int j = i % (DDIM / 4);
    int s0 = g_slot[2 * t], s1 = g_slot[2 * t + 1];
    float w0 = g_wt[2 * t], w1 = g_wt[2 * t + 1];
    float4 y0 = ((const float4*)(g_y + (size_t)s0 * DDIM))[j];
    float4 y1 = ((const float4*)(g_y + (size_t)s1 * DDIM))[j];
    float4 o;
    o.x = w0 * y0.x + w1 * y1.x;
    o.y = w0 * y0.y + w1 * y1.y;
    o.z = w0 * y0.z + w1 * y1.z;
    o.w = w0 * y0.w + w1 * y1.w;
    ((float4*)out)[i] = o;
}

// ---------------- launch ----------------
extern "C" void kernel_launch(void* const* d_in, const int* in_sizes, int n_in,
                              void* d_out, int out_size) {
    const float* x  = (const float*)d_in[0];
    const float* Wg = (const float*)d_in[1];
    const float* W1 = (const float*)d_in[2];
    const float* b1 = (const float*)d_in[3];
    const float* W2 = (const float*)d_in[4];
    const float* b2 = (const float*)d_in[5];
    float* out = (float*)d_out;
    int T = in_sizes[0] / DDIM;   // 8192

    __half *s_xh, *s_w1t, *s_w2t;
    cudaGetSymbolAddress((void**)&s_xh,  g_xh);
    cudaGetSymbolAddress((void**)&s_w1t, g_w1t);
    cudaGetSymbolAddress((void**)&s_w2t, g_w2t);
    cudaFuncSetAttribute(gemm_f16<DDIM, HDIM, true,  true >,
                         cudaFuncAttributeMaxDynamicSharedMemorySize, SMEM_GEMM);
    cudaFuncSetAttribute(gemm_f16<HDIM, DDIM, false, false>,
                         cudaFuncAttributeMaxDynamicSharedMemorySize, SMEM_GEMM);

    init_kernel<<<1, 32>>>();

    int nx = T * DDIM / 4;
    cvt_h_kernel<<<(nx + 255) / 256, 256>>>(x, s_xh, nx);
    dim3 tb(32, 8);
    transpose_h_kernel<<<dim3(DDIM / 32, HDIM / 32, NEXP), tb>>>(W1, s_w1t, DDIM, HDIM);
    transpose_h_kernel<<<dim3(HDIM / 32, DDIM / 32, NEXP), tb>>>(W2, s_w2t, HDIM, DDIM);

    router_kernel<<<(T + 7) / 8, 256>>>(x, Wg, T);
    offsets_kernel<<<1, 32>>>();
    scatter_kernel<<<(T + 255) / 256, 256>>>(T);

    dim3 grid1(HDIM / BN, SLOT_MAX / BM);   // 8 x 136
    gemm_f16<DDIM, HDIM, true,  true ><<<grid1, 512, SMEM_GEMM>>>(s_xh, s_w1t, b1);

    dim3 grid2(DDIM / BN, SLOT_MAX / BM);   // 4 x 136
    gemm_f16<HDIM, DDIM, false, false><<<grid2, 512, SMEM_GEMM>>>(nullptr, s_w2t, b2);

    int nvec = T * (DDIM / 4);
    combine_kernel<<<(nvec + 255) / 256, 256>>>(out, T);
}